// round 10
// baseline (speedup 1.0000x reference)
#include <cuda_runtime.h>
#include <cuda_fp16.h>
#include <cstdint>
#include <math.h>

#define Bc 8
#define Hh 8
#define Dd 512
#define HD 64
#define LNS 64
#define LS 2048
#define LSO 512
#define LQ (LSO + LNS)   // 576
#define LK (LS + LNS)    // 2112
#define LL (LS + LNS)
#define DELTA (LK - LQ)  // 1536

__device__ float g_Q[(size_t)Bc * Hh * LQ * HD];
__device__ float g_attn[(size_t)Bc * LQ * Dd];
// fp16 K: [bh][key][dim2] packed dim-pairs; fp16 V transposed: [bh][dim][key]
__device__ unsigned g_Kh[(size_t)Bc * Hh * LK * 32];
__device__ __half   g_Vt[(size_t)Bc * Hh * HD * LK];
// packed fp16x2 split GEMM operands, row-major [row][k2=256]
__device__ unsigned g_x2h[(size_t)Bc * LS * 256];
__device__ unsigned g_x2l[(size_t)Bc * LS * 256];
__device__ unsigned g_w2h[(size_t)4 * Dd * 256];   // W^T [mat][n][k2]
__device__ unsigned g_a2h[(size_t)Bc * LQ * 256];
__device__ unsigned g_a2l[(size_t)Bc * LQ * 256];

// ---------------- helpers ----------------
__device__ __forceinline__ void mma16h(float* c, const unsigned* a, const unsigned* b) {
    asm volatile("mma.sync.aligned.m16n8k16.row.col.f32.f16.f16.f32 "
        "{%0,%1,%2,%3},{%4,%5,%6,%7},{%8,%9},{%0,%1,%2,%3};\n"
        : "+f"(c[0]), "+f"(c[1]), "+f"(c[2]), "+f"(c[3])
        : "r"(a[0]), "r"(a[1]), "r"(a[2]), "r"(a[3]), "r"(b[0]), "r"(b[1]));
}
__device__ __forceinline__ void cp16(uint32_t sdst, const void* gsrc) {
    asm volatile("cp.async.ca.shared.global [%0], [%1], 16;\n" :: "r"(sdst), "l"(gsrc));
}
__device__ __forceinline__ void cp_commit() { asm volatile("cp.async.commit_group;\n" ::: "memory"); }
__device__ __forceinline__ void cp_wait1()  { asm volatile("cp.async.wait_group 1;\n" ::: "memory"); }
__device__ __forceinline__ uint32_t smem_u32(const void* p) {
    uint32_t a; asm("{ .reg .u64 t; cvta.to.shared.u64 t, %1; cvt.u32.u64 %0, t; }" : "=r"(a) : "l"(p)); return a;
}
__device__ __forceinline__ unsigned packh(float f0, float f1) {
    __half2 hh = __floats2half2_rn(f0, f1);
    return *reinterpret_cast<unsigned*>(&hh);
}
__device__ __forceinline__ void split2h(float f0, float f1, unsigned& h, unsigned& l) {
    __half2 hh = __floats2half2_rn(f0, f1);
    float r0 = f0 - __half2float(__low2half(hh));
    float r1 = f1 - __half2float(__high2half(hh));
    h = *reinterpret_cast<unsigned*>(&hh);
    l = packh(r0, r1);
}

// ---------------- converters ----------------
__global__ __launch_bounds__(256) void conv_in(
    const float* __restrict__ x, const float* __restrict__ w0, const float* __restrict__ w1,
    const float* __restrict__ w2, const float* __restrict__ w3)
{
    const int gid = blockIdx.x * 256 + threadIdx.x;
    if (blockIdx.x < 8192) {
        const int row = gid >> 7, col = (gid & 127) << 2;
        const int b = row >> 11, t = row & 2047;
        float4 v = *(const float4*)(x + ((size_t)b * LL + t) * Dd + col);
        unsigned h0, l0, h1, l1;
        split2h(v.x, v.y, h0, l0);
        split2h(v.z, v.w, h1, l1);
        *(uint2*)&g_x2h[(size_t)row * 256 + (col >> 1)] = make_uint2(h0, h1);
        *(uint2*)&g_x2l[(size_t)row * 256 + (col >> 1)] = make_uint2(l0, l1);
    } else {
        const int idx = gid - 8192 * 256;
        if (idx >= 4 * 512 * 64) return;
        const int n = idx & 511, k8 = (idx >> 9) & 63, mat = idx >> 15;
        const float* W = (mat == 0) ? w0 : (mat == 1) ? w1 : (mat == 2) ? w2 : w3;
        unsigned hh[4];
        #pragma unroll
        for (int j = 0; j < 4; j++)
            hh[j] = packh(W[(size_t)(k8 * 8 + 2 * j) * Dd + n],
                          W[(size_t)(k8 * 8 + 2 * j + 1) * Dd + n]);
        *(uint4*)&g_w2h[((size_t)mat * 512 + n) * 256 + k8 * 4] =
            make_uint4(hh[0], hh[1], hh[2], hh[3]);
    }
}

__global__ __launch_bounds__(256) void conv_attn(const float* __restrict__ A)
{
    const int gid = blockIdx.x * 256 + threadIdx.x;
    const int row = gid >> 7, col = (gid & 127) << 2;
    float4 v = *(const float4*)(A + (size_t)row * Dd + col);
    unsigned h0, l0, h1, l1;
    split2h(v.x, v.y, h0, l0);
    split2h(v.z, v.w, h1, l1);
    *(uint2*)&g_a2h[(size_t)row * 256 + (col >> 1)] = make_uint2(h0, h1);
    *(uint2*)&g_a2l[(size_t)row * 256 + (col >> 1)] = make_uint2(l0, l1);
}

// ---------------- pipelined 2-term fp16 GEMM ----------------
#define B_AH 0u
#define B_AL 20480u
#define B_BH 40960u
#define GS_TOT 51200

__global__ __launch_bounds__(256) void gemm5(
    const float* __restrict__ biasK, const float* __restrict__ biasV,
    const float* __restrict__ biasQ, float* __restrict__ OutP,
    int qkvMode)
{
    const int m0 = blockIdx.y << 7, n0 = blockIdx.x << 6;
    int widx, bt, tok_off, omode;
    const float* bias;
    if (qkvMode) {
        const int z = blockIdx.z;
        if (z == 2 && blockIdx.y >= 32) return;
        if (z == 0)      { widx = 1; bias = biasK; bt = LS;  tok_off = 0;        omode = 2; }
        else if (z == 1) { widx = 2; bias = biasV; bt = LS;  tok_off = 0;        omode = 3; }
        else             { widx = 0; bias = biasQ; bt = LSO; tok_off = LS - LSO; omode = 1; }
    } else {
        widx = 3; bias = biasK; bt = LQ; tok_off = 0; omode = 0;
    }

    extern __shared__ __align__(16) char smem[];
    const uint32_t sb = smem_u32(smem);
    const int tid = threadIdx.x;
    const int lane = tid & 31, warp = tid >> 5;
    const int wm = warp >> 1, wn = warp & 1;
    const int g = lane >> 2, tg = lane & 3;

    const int arow0 = qkvMode ? ((m0 / bt) * LS + tok_off + (m0 % bt)) : m0;
    const char* aH = (const char*)(qkvMode ? g_x2h : g_a2h) + (size_t)arow0 * 1024;
    const char* aL = (const char*)(qkvMode ? g_x2l : g_a2l) + (size_t)arow0 * 1024;
    const char* bH = (const char*)g_w2h + ((size_t)widx * 512 + n0) * 1024;

    const int arow = tid >> 1;
    const int ach0 = (tid & 1) * 2;
    const int brow = tid >> 2;
    const int bch  = tid & 3;

    float acc[2][4][4];
    #pragma unroll
    for (int a = 0; a < 2; a++)
        #pragma unroll
        for (int b = 0; b < 4; b++)
            #pragma unroll
            for (int c = 0; c < 4; c++) acc[a][b][c] = 0.f;

#define G_LOAD(c, st) { \
    const size_t ao = (size_t)arow * 1024 + (size_t)(c) * 64; \
    cp16(sb + B_AH + (st) * 10240u + arow * 80 + (ach0 + 0) * 16, aH + ao + (ach0 + 0) * 16); \
    cp16(sb + B_AH + (st) * 10240u + arow * 80 + (ach0 + 1) * 16, aH + ao + (ach0 + 1) * 16); \
    cp16(sb + B_AL + (st) * 10240u + arow * 80 + (ach0 + 0) * 16, aL + ao + (ach0 + 0) * 16); \
    cp16(sb + B_AL + (st) * 10240u + arow * 80 + (ach0 + 1) * 16, aL + ao + (ach0 + 1) * 16); \
    cp16(sb + B_BH + (st) * 5120u + brow * 80 + bch * 16, \
         bH + (size_t)brow * 1024 + (size_t)(c) * 64 + bch * 16); \
    cp_commit(); }

    G_LOAD(0, 0);

    for (int c = 0; c < 16; c++) {
        const int nc = (c + 1 < 16) ? c + 1 : 15;
        G_LOAD(nc, (c + 1) & 1);
        cp_wait1();
        __syncthreads();

        const unsigned* A_h = (const unsigned*)(smem + B_AH + (c & 1) * 10240u);
        const unsigned* A_l = (const unsigned*)(smem + B_AL + (c & 1) * 10240u);
        const unsigned* Bh_ = (const unsigned*)(smem + B_BH + (c & 1) * 5120u);

        #pragma unroll
        for (int s2 = 0; s2 < 2; s2++) {
            const int k2o = s2 * 8;
            unsigned ah[2][4], al[2][4], bh[4][2];
            #pragma unroll
            for (int mt = 0; mt < 2; mt++) {
                const int mr = wm * 32 + mt * 16;
                ah[mt][0] = A_h[(mr + g) * 20 + k2o + tg];
                ah[mt][1] = A_h[(mr + g + 8) * 20 + k2o + tg];
                ah[mt][2] = A_h[(mr + g) * 20 + k2o + tg + 4];
                ah[mt][3] = A_h[(mr + g + 8) * 20 + k2o + tg + 4];
                al[mt][0] = A_l[(mr + g) * 20 + k2o + tg];
                al[mt][1] = A_l[(mr + g + 8) * 20 + k2o + tg];
                al[mt][2] = A_l[(mr + g) * 20 + k2o + tg + 4];
                al[mt][3] = A_l[(mr + g + 8) * 20 + k2o + tg + 4];
            }
            #pragma unroll
            for (int nt = 0; nt < 4; nt++) {
                const int nc2 = wn * 32 + nt * 8 + g;
                bh[nt][0] = Bh_[nc2 * 20 + k2o + tg];
                bh[nt][1] = Bh_[nc2 * 20 + k2o + tg + 4];
            }
            #pragma unroll
            for (int mt = 0; mt < 2; mt++)
                #pragma unroll
                for (int nt = 0; nt < 4; nt++) {
                    mma16h(acc[mt][nt], ah[mt], bh[nt]);
                    mma16h(acc[mt][nt], al[mt], bh[nt]);
                }
        }
        __syncthreads();
    }

    #pragma unroll
    for (int mt = 0; mt < 2; mt++)
        #pragma unroll
        for (int j2 = 0; j2 < 2; j2++) {
            const int m = m0 + wm * 32 + mt * 16 + g + j2 * 8;
            const int b = m / bt, t = m % bt;
            #pragma unroll
            for (int nt = 0; nt < 4; nt++) {
                const int n = n0 + wn * 32 + nt * 8 + 2 * tg;
                const float c0 = acc[mt][nt][j2 * 2 + 0] + bias[n];
                const float c1 = acc[mt][nt][j2 * 2 + 1] + bias[n + 1];
                const int h = n >> 6, dd = n & 63;
                if (omode == 0) {
                    *(float2*)&OutP[(size_t)m * Dd + n] = make_float2(c0, c1);
                } else if (omode == 1) {
                    *(float2*)&g_Q[(((size_t)b * Hh + h) * LQ + t) * HD + dd] = make_float2(c0, c1);
                } else if (omode == 2) {
                    g_Kh[(((size_t)b * Hh + h) * LK + t) * 32 + (dd >> 1)] = packh(c0, c1);
                } else {
                    g_Vt[(((size_t)b * Hh + h) * HD + dd) * LK + t]     = __float2half(c0);
                    g_Vt[(((size_t)b * Hh + h) * HD + dd + 1) * LK + t] = __float2half(c1);
                }
            }
        }
}

// ---------------- per-token projections (fused 3-in-1) ----------------
__global__ __launch_bounds__(256) void ns_proj(
    const float* __restrict__ x,
    const float* __restrict__ nw0, const float* __restrict__ nb0, float* __restrict__ o0,
    const float* __restrict__ nw1, const float* __restrict__ nb1,
    const float* __restrict__ nw2, const float* __restrict__ nb2)
{
    const int z = blockIdx.z;
    const float* nw = (z == 0) ? nw0 : (z == 1) ? nw1 : nw2;
    const float* nb = (z == 0) ? nb0 : (z == 1) ? nb1 : nb2;

    const int n = blockIdx.x, tid = threadIdx.x;
    const int cgrp = tid & 31, kh = tid >> 5, kbeg = kh * 64;
    const int colb = blockIdx.y * 128;

    __shared__ float xs[8][512];
    __shared__ float red[8][8][128];

    for (int i = tid; i < 8 * 512; i += 256) {
        const int b = i >> 9, k = i & 511;
        xs[b][k] = x[((size_t)b * LL + LS + n) * Dd + k];
    }
    __syncthreads();

    const float4* wp4 = (const float4*)(nw + (size_t)n * Dd * Dd) + (colb >> 2) + cgrp;
    float acc[8][4];
    #pragma unroll
    for (int b = 0; b < 8; b++)
        #pragma unroll
        for (int j = 0; j < 4; j++) acc[b][j] = 0.f;

    for (int k = 0; k < 64; k += 4) {
        float4 w[4];
        #pragma unroll
        for (int u = 0; u < 4; u++) w[u] = wp4[(size_t)(kbeg + k + u) * 128];
        #pragma unroll
        for (int u = 0; u < 4; u++)
            #pragma unroll
            for (int b = 0; b < 8; b++) {
                const float s = xs[b][kbeg + k + u];
                acc[b][0] += s * w[u].x; acc[b][1] += s * w[u].y;
                acc[b][2] += s * w[u].z; acc[b][3] += s * w[u].w;
            }
    }
    #pragma unroll
    for (int b = 0; b < 8; b++)
        *(float4*)&red[kh][b][cgrp * 4] = make_float4(acc[b][0], acc[b][1], acc[b][2], acc[b][3]);
    __syncthreads();

    if (z == 1) {   // K: packed dim pairs
        for (int i = tid; i < 8 * 64; i += 256) {
            const int b = i >> 6, cp = (i & 63) * 2;
            float s0 = 0.f, s1 = 0.f;
            #pragma unroll
            for (int k8 = 0; k8 < 8; k8++) { s0 += red[k8][b][cp]; s1 += red[k8][b][cp + 1]; }
            const int col = colb + cp, h = col >> 6, dd = col & 63;
            s0 += nb[(size_t)n * Dd + col];
            s1 += nb[(size_t)n * Dd + col + 1];
            g_Kh[(((size_t)b * Hh + h) * LK + (LS + n)) * 32 + (dd >> 1)] = packh(s0, s1);
        }
    } else {
        for (int i = tid; i < 8 * 128; i += 256) {
            const int b = i >> 7, c = i & 127;
            float s = 0.f;
            #pragma unroll
            for (int k8 = 0; k8 < 8; k8++) s += red[k8][b][c];
            const int col = colb + c, h = col >> 6, dd = col & 63;
            const float v = s + nb[(size_t)n * Dd + col];
            if (z == 0)
                o0[(((size_t)b * Hh + h) * LQ + LSO + n) * HD + dd] = v;
            else
                g_Vt[(((size_t)b * Hh + h) * HD + dd) * LK + (LS + n)] = __float2half(v);
        }
    }
}

// ---------------- flash attention, full fp16 MMA ----------------
// smem: K [2][64 keys][144B], V [2][64 dims][144B], pads [2][64] int
#define AS_V 18432u
#define AS_P 36864u
#define ATTN_SMEM 37376

__global__ __launch_bounds__(128) void attn_tc(
    const float* __restrict__ Q, const int* __restrict__ pad_mask,
    float* __restrict__ Outp)
{
    extern __shared__ __align__(16) char smc[];
    const uint32_t sb = smem_u32(smc);
    int* padi = (int*)(smc + AS_P);

    const int tid = threadIdx.x, lane = tid & 31, warp = tid >> 5;
    const int g = lane >> 2, tg = lane & 3;
    const int bh = blockIdx.y, b = bh >> 3, h = bh & 7;
    const int q0 = blockIdx.x << 6;
    const int mr = warp * 16;

    const float* Qp = Q + ((size_t)bh * LQ + q0) * HD;
    const char* Kbp = (const char*)g_Kh + (size_t)bh * LK * 128;
    const char* Vbp = (const char*)g_Vt + (size_t)bh * HD * LK * 2;

    // Q fragments: fp16, scale folded
    unsigned aq[4][4];
    {
        const float* q0p = Qp + (size_t)(mr + g) * HD;
        const float* q1p = Qp + (size_t)(mr + g + 8) * HD;
        #pragma unroll
        for (int kc = 0; kc < 4; kc++) {
            aq[kc][0] = packh(q0p[kc * 16 + 2 * tg] * 0.125f, q0p[kc * 16 + 2 * tg + 1] * 0.125f);
            aq[kc][1] = packh(q1p[kc * 16 + 2 * tg] * 0.125f, q1p[kc * 16 + 2 * tg + 1] * 0.125f);
            aq[kc][2] = packh(q0p[kc * 16 + 8 + 2 * tg] * 0.125f, q0p[kc * 16 + 9 + 2 * tg] * 0.125f);
            aq[kc][3] = packh(q1p[kc * 16 + 8 + 2 * tg] * 0.125f, q1p[kc * 16 + 9 + 2 * tg] * 0.125f);
        }
    }

    float o[8][4];
    #pragma unroll
    for (int nt = 0; nt < 8; nt++)
        #pragma unroll
        for (int j = 0; j < 4; j++) o[nt][j] = 0.f;
    float m_run[2] = {-1e30f, -1e30f};
    float l_run[2] = {0.f, 0.f};

    const int row0 = q0 + mr + g;
    const int ntiles = min(LK >> 6, ((q0 + 63 + DELTA) >> 6) + 1);

#define A_LOAD(t, st) { \
    _Pragma("unroll") \
    for (int i = 0; i < 4; i++) { \
        const int idx = i * 128 + tid; \
        const int r = idx >> 3, ch = idx & 7; \
        cp16(sb + (st) * 9216u + r * 144u + ch * 16u, \
             Kbp + ((size_t)((t) * 64 + r)) * 128 + ch * 16); \
        cp16(sb + AS_V + (st) * 9216u + r * 144u + ch * 16u, \
             Vbp + (size_t)r * (LK * 2) + (t) * 128 + ch * 16); \
    } \
    if ((t) * 64 < LS) { \
        if (tid < 16) \
            cp16(sb + AS_P + (st) * 256u + tid * 16u, \
                 (const char*)(pad_mask + (size_t)b * LS + (t) * 64) + tid * 16); \
    } else { \
        if (tid < 64) padi[(st) * 64 + tid] = 1; \
    } \
    cp_commit(); }

    A_LOAD(0, 0);

    for (int kt = 0; kt < ntiles; kt++) {
        const int nxt = (kt + 1 < ntiles) ? kt + 1 : ntiles - 1;
        A_LOAD(nxt, (kt + 1) & 1);
        cp_wait1();
        __syncthreads();

        const unsigned* Kc = (const unsigned*)(smc + (kt & 1) * 9216u);
        const unsigned* Vc = (const unsigned*)(smc + AS_V + (kt & 1) * 9216u);
        const int*      pc = padi + (kt & 1) * 64;
        const int k0 = kt << 6;

        // ---- S = Q K^T (fp16) ----
        float sc[8][4];
        #pragma unroll
        for (int nt = 0; nt < 8; nt++)
            #pragma unroll
            for (int j = 0; j < 4; j++) sc[nt][j] = 0.f;

        #pragma unroll
        for (int kc = 0; kc < 4; kc++)
            #pragma unroll
            for (int nt = 0; nt < 8; nt++) {
                unsigned bb[2];
                bb[0] = Kc[(nt * 8 + g) * 36 + kc * 8 + tg];
                bb[1] = Kc[(nt * 8 + g) * 36 + kc * 8 + tg + 4];
                mma16h(sc[nt], aq[kc], bb);
            }

        // ---- mask + online softmax ----
        float mx0 = -1e30f, mx1 = -1e30f;
        #pragma unroll
        for (int nt = 0; nt < 8; nt++) {
            const int cb = k0 + nt * 8 + 2 * tg;
            const int p0 = pc[nt * 8 + 2 * tg];
            const int p1 = pc[nt * 8 + 2 * tg + 1];
            if (cb     > row0 + DELTA     || !p0) sc[nt][0] = -1e9f;
            if (cb + 1 > row0 + DELTA     || !p1) sc[nt][1] = -1e9f;
            if (cb     > row0 + 8 + DELTA || !p0) sc[nt][2] = -1e9f;
            if (cb + 1 > row0 + 8 + DELTA || !p1) sc[nt][3] = -1e9f;
            mx0 = fmaxf(mx0, fmaxf(sc[nt][0], sc[nt][1]));
            mx1 = fmaxf(mx1, fmaxf(sc[nt][2], sc[nt][3]));
        }
        mx0 = fmaxf(mx0, __shfl_xor_sync(0xffffffffu, mx0, 1));
        mx0 = fmaxf(mx0, __shfl_xor_sync(0xffffffffu, mx0, 2));
        mx1 = fmaxf(mx1, __shfl_xor_sync(0xffffffffu, mx1, 1));
        mx1 = fmaxf(mx1, __shfl_xor_sync(0xffffffffu, mx1, 2));

        const float mn0 = fmaxf(m_run[0], mx0), mn1 = fmaxf(m_run[1], mx1);
        const float cr0 = __expf(m_run[0] - mn0), cr1 = __expf(m_run[1] - mn1);

        float ls0 = 0.f, ls1 = 0.f;
        #pragma unroll
        for (int nt = 0; nt < 8; nt++) {
            sc[nt][0] = __expf(sc[nt][0] - mn0); ls0 += sc[nt][0];
            sc[nt][1] = __expf(sc[nt][1] - mn0); ls0 += sc[nt][1];
            sc[nt][2] = __expf(sc[nt][2] - mn1); ls1 += sc[nt][2];
            sc[nt][3] = __expf(sc[nt][3] - mn1); ls1 += sc[nt][3];
        }
        ls0 += __shfl_xor_sync(0xffffffffu, ls0, 1);
        ls0 += __shfl_xor_sync(0xffffffffu, ls0, 2);
        ls1 += __shfl_xor_sync(0xffffffffu, ls1, 1);
        ls1 += __shfl_xor_sync(0xffffffffu, ls1, 2);

        l_run[0] = l_run[0] * cr0 + ls0;
        l_run[1] = l_run[1] * cr1 + ls1;
        m_run[0] = mn0; m_run[1] = mn1;

        #pragma unroll
        for (int nt = 0; nt < 8; nt++) {
            o[nt][0] *= cr0; o[nt][1] *= cr0;
            o[nt][2] *= cr1; o[nt][3] *= cr1;
        }

        // ---- O += P V  (C-fragment == A-fragment: pure packs, no shuffles) ----
        #pragma unroll
        for (int kc = 0; kc < 4; kc++) {
            unsigned a[4];
            a[0] = packh(sc[2 * kc][0], sc[2 * kc][1]);
            a[1] = packh(sc[2 * kc][2], sc[2 * kc][3]);
            a[2] = packh(sc[2 * kc + 1][0], sc[2 * kc + 1][1]);
            a[3] = packh(sc[2 * kc + 1][2], sc[2 * kc + 1][3]);
            #pragma unroll
            for (int nt = 0; nt < 8; nt++) {
                unsigned bb[2];
                bb[0] = Vc[(nt * 8 + g) * 36 + kc * 8 + tg];
                bb[1] = Vc[(nt * 8 + g) * 36 + kc * 8 + tg + 4];
                mma16h(o[nt], a, bb);
            }
        }
        __syncthreads();
    }

    const float inv0 = (l_run[0] > 0.f) ? 1.f / l_run[0] : 0.f;
    const float inv1 = (l_run[1] > 0.f) ? 1.f / l_run[1] : 0.f;
    float* op0 = Outp + ((size_t)b * LQ + row0) * Dd + h * HD;
    float* op1 = op0 + (size_t)8 * Dd;
    #pragma unroll
    for (int nt = 0; nt < 8; nt++) {
        const int dc = nt * 8 + 2 * tg;
        *(float2*)(op0 + dc) = make_float2(o[nt][0] * inv0, o[nt][1] * inv0);
        *(float2*)(op1 + dc) = make_float2(o[nt][2] * inv1, o[nt][3] * inv1);
    }
}

// ---------------------------------------------------------------------------
extern "C" void kernel_launch(void* const* d_in, const int* in_sizes, int n_in,
                              void* d_out, int out_size)
{
    const float* x        = (const float*)d_in[0];
    const int*   pad_mask = (const int*)  d_in[1];
    const float* wq_sw = (const float*)d_in[4];
    const float* wq_sb = (const float*)d_in[5];
    const float* wq_nw = (const float*)d_in[6];
    const float* wq_nb = (const float*)d_in[7];
    const float* wk_sw = (const float*)d_in[8];
    const float* wk_sb = (const float*)d_in[9];
    const float* wk_nw = (const float*)d_in[10];
    const float* wk_nb = (const float*)d_in[11];
    const float* wv_sw = (const float*)d_in[12];
    const float* wv_sb = (const float*)d_in[13];
    const float* wv_nw = (const float*)d_in[14];
    const float* wv_nb = (const float*)d_in[15];
    const float* out_w = (const float*)d_in[16];
    const float* out_b = (const float*)d_in[17];
    float* out = (float*)d_out;

    float *pQ, *pA;
    cudaGetSymbolAddress((void**)&pQ, g_Q);
    cudaGetSymbolAddress((void**)&pA, g_attn);

    cudaFuncSetAttribute(gemm5, cudaFuncAttributeMaxDynamicSharedMemorySize, GS_TOT);
    cudaFuncSetAttribute(attn_tc, cudaFuncAttributeMaxDynamicSharedMemorySize, ATTN_SMEM);

    // 1: pre-split x (fp16 hi/lo) + 4 weight matrices (fp16 hi)
    conv_in<<<8704, 256>>>(x, wq_sw, wk_sw, wv_sw, out_w);
    // 2: fused Q+K+V projections; K/V written fp16 pre-packed for attention
    gemm5<<<dim3(8, 128, 3), 256, GS_TOT>>>(wk_sb, wv_sb, wq_sb, 0, 1);
    // 3: per-token projections (fused)
    ns_proj<<<dim3(64, 4, 3), 256>>>(x, wq_nw, wq_nb, pQ, wk_nw, wk_nb, wv_nw, wv_nb);
    // 4: attention (fp16 MMA)  <-- profiled slot
    attn_tc<<<dim3(LQ / 64, Bc * Hh), 128, ATTN_SMEM>>>(pQ, pad_mask, pA);
    // 5: split attn output
    conv_attn<<<2304, 256>>>(pA);
    // 6: output projection
    gemm5<<<dim3(8, 36, 1), 256, GS_TOT>>>(out_b, 0, 0, out, 0);
}

// round 13
// speedup vs baseline: 1.4805x; 1.4805x over previous
#include <cuda_runtime.h>
#include <cuda_fp16.h>
#include <cstdint>
#include <math.h>

#define Bc 8
#define Hh 8
#define Dd 512
#define HD 64
#define LNS 64
#define LS 2048
#define LSO 512
#define LQ (LSO + LNS)   // 576
#define LK (LS + LNS)    // 2112
#define LL (LS + LNS)
#define DELTA (LK - LQ)  // 1536

__device__ float g_Q[(size_t)Bc * Hh * LQ * HD];
// fp16 K: [bh][key][dim2] packed dim-pairs; fp16 V transposed: [bh][dim][key]
__device__ unsigned g_Kh[(size_t)Bc * Hh * LK * 32];
__device__ __half   g_Vt[(size_t)Bc * Hh * HD * LK];
// packed fp16x2 split GEMM operands, row-major [row][k2=256]
__device__ unsigned g_x2h[(size_t)Bc * LS * 256];
__device__ unsigned g_x2l[(size_t)Bc * LS * 256];
__device__ unsigned g_w2h[(size_t)4 * Dd * 256];   // W^T [mat][n][k2]
__device__ unsigned g_a2h[(size_t)Bc * LQ * 256];
__device__ unsigned g_a2l[(size_t)Bc * LQ * 256];

// ---------------- helpers ----------------
__device__ __forceinline__ void mma16h(float* c, const unsigned* a, const unsigned* b) {
    asm volatile("mma.sync.aligned.m16n8k16.row.col.f32.f16.f16.f32 "
        "{%0,%1,%2,%3},{%4,%5,%6,%7},{%8,%9},{%0,%1,%2,%3};\n"
        : "+f"(c[0]), "+f"(c[1]), "+f"(c[2]), "+f"(c[3])
        : "r"(a[0]), "r"(a[1]), "r"(a[2]), "r"(a[3]), "r"(b[0]), "r"(b[1]));
}
__device__ __forceinline__ void cp16(uint32_t sdst, const void* gsrc) {
    asm volatile("cp.async.ca.shared.global [%0], [%1], 16;\n" :: "r"(sdst), "l"(gsrc));
}
__device__ __forceinline__ void cp_commit() { asm volatile("cp.async.commit_group;\n" ::: "memory"); }
__device__ __forceinline__ void cp_wait1()  { asm volatile("cp.async.wait_group 1;\n" ::: "memory"); }
__device__ __forceinline__ uint32_t smem_u32(const void* p) {
    uint32_t a; asm("{ .reg .u64 t; cvta.to.shared.u64 t, %1; cvt.u32.u64 %0, t; }" : "=r"(a) : "l"(p)); return a;
}
__device__ __forceinline__ unsigned packh(float f0, float f1) {
    __half2 hh = __floats2half2_rn(f0, f1);
    return *reinterpret_cast<unsigned*>(&hh);
}
__device__ __forceinline__ void split2h(float f0, float f1, unsigned& h, unsigned& l) {
    __half2 hh = __floats2half2_rn(f0, f1);
    float r0 = f0 - __half2float(__low2half(hh));
    float r1 = f1 - __half2float(__high2half(hh));
    h = *reinterpret_cast<unsigned*>(&hh);
    l = packh(r0, r1);
}

// ---------------- converters ----------------
__global__ __launch_bounds__(256) void conv_in(
    const float* __restrict__ x, const float* __restrict__ w0, const float* __restrict__ w1,
    const float* __restrict__ w2, const float* __restrict__ w3)
{
    const int gid = blockIdx.x * 256 + threadIdx.x;
    if (blockIdx.x < 8192) {
        const int row = gid >> 7, col = (gid & 127) << 2;
        const int b = row >> 11, t = row & 2047;
        float4 v = *(const float4*)(x + ((size_t)b * LL + t) * Dd + col);
        unsigned h0, l0, h1, l1;
        split2h(v.x, v.y, h0, l0);
        split2h(v.z, v.w, h1, l1);
        *(uint2*)&g_x2h[(size_t)row * 256 + (col >> 1)] = make_uint2(h0, h1);
        *(uint2*)&g_x2l[(size_t)row * 256 + (col >> 1)] = make_uint2(l0, l1);
    } else {
        const int idx = gid - 8192 * 256;
        if (idx >= 4 * 512 * 64) return;
        const int n = idx & 511, k8 = (idx >> 9) & 63, mat = idx >> 15;
        const float* W = (mat == 0) ? w0 : (mat == 1) ? w1 : (mat == 2) ? w2 : w3;
        unsigned hh[4];
        #pragma unroll
        for (int j = 0; j < 4; j++)
            hh[j] = packh(W[(size_t)(k8 * 8 + 2 * j) * Dd + n],
                          W[(size_t)(k8 * 8 + 2 * j + 1) * Dd + n]);
        *(uint4*)&g_w2h[((size_t)mat * 512 + n) * 256 + k8 * 4] =
            make_uint4(hh[0], hh[1], hh[2], hh[3]);
    }
}

// ---------------- pipelined 2-term fp16 GEMM ----------------
#define B_AH 0u
#define B_AL 20480u
#define B_BH 40960u
#define GS_TOT 51200

__global__ __launch_bounds__(256) void gemm5(
    const float* __restrict__ biasK, const float* __restrict__ biasV,
    const float* __restrict__ biasQ, float* __restrict__ OutP,
    int qkvMode)
{
    const int m0 = blockIdx.y << 7, n0 = blockIdx.x << 6;
    int widx, bt, omode;
    const float* bias;
    if (qkvMode) {
        const int z = blockIdx.z;
        if (z == 2 && blockIdx.y >= 32) return;
        if (z == 0)      { widx = 1; bias = biasK; bt = LS;  omode = 2; }
        else if (z == 1) { widx = 2; bias = biasV; bt = LS;  omode = 3; }
        else             { widx = 0; bias = biasQ; bt = LSO; omode = 1; }
    } else {
        widx = 3; bias = biasK; bt = LQ; omode = 0;
    }
    const int tok_off = (omode == 1) ? (LS - LSO) : 0;

    extern __shared__ __align__(16) char smem[];
    const uint32_t sb = smem_u32(smem);
    const int tid = threadIdx.x;
    const int lane = tid & 31, warp = tid >> 5;
    const int wm = warp >> 1, wn = warp & 1;
    const int g = lane >> 2, tg = lane & 3;

    const int arow0 = qkvMode ? ((m0 / bt) * LS + tok_off + (m0 % bt)) : m0;
    const char* aH = (const char*)(qkvMode ? g_x2h : g_a2h) + (size_t)arow0 * 1024;
    const char* aL = (const char*)(qkvMode ? g_x2l : g_a2l) + (size_t)arow0 * 1024;
    const char* bH = (const char*)g_w2h + ((size_t)widx * 512 + n0) * 1024;

    const int arow = tid >> 1;
    const int ach0 = (tid & 1) * 2;
    const int brow = tid >> 2;
    const int bch  = tid & 3;

    float acc[2][4][4];
    #pragma unroll
    for (int a = 0; a < 2; a++)
        #pragma unroll
        for (int b = 0; b < 4; b++)
            #pragma unroll
            for (int c = 0; c < 4; c++) acc[a][b][c] = 0.f;

#define G_LOAD(c, st) { \
    const size_t ao = (size_t)arow * 1024 + (size_t)(c) * 64; \
    cp16(sb + B_AH + (st) * 10240u + arow * 80 + (ach0 + 0) * 16, aH + ao + (ach0 + 0) * 16); \
    cp16(sb + B_AH + (st) * 10240u + arow * 80 + (ach0 + 1) * 16, aH + ao + (ach0 + 1) * 16); \
    cp16(sb + B_AL + (st) * 10240u + arow * 80 + (ach0 + 0) * 16, aL + ao + (ach0 + 0) * 16); \
    cp16(sb + B_AL + (st) * 10240u + arow * 80 + (ach0 + 1) * 16, aL + ao + (ach0 + 1) * 16); \
    cp16(sb + B_BH + (st) * 5120u + brow * 80 + bch * 16, \
         bH + (size_t)brow * 1024 + (size_t)(c) * 64 + bch * 16); \
    cp_commit(); }

    G_LOAD(0, 0);

    for (int c = 0; c < 16; c++) {
        const int nc = (c + 1 < 16) ? c + 1 : 15;
        G_LOAD(nc, (c + 1) & 1);
        cp_wait1();
        __syncthreads();

        const unsigned* A_h = (const unsigned*)(smem + B_AH + (c & 1) * 10240u);
        const unsigned* A_l = (const unsigned*)(smem + B_AL + (c & 1) * 10240u);
        const unsigned* Bh_ = (const unsigned*)(smem + B_BH + (c & 1) * 5120u);

        #pragma unroll
        for (int s2 = 0; s2 < 2; s2++) {
            const int k2o = s2 * 8;
            unsigned ah[2][4], al[2][4], bh[4][2];
            #pragma unroll
            for (int mt = 0; mt < 2; mt++) {
                const int mr = wm * 32 + mt * 16;
                ah[mt][0] = A_h[(mr + g) * 20 + k2o + tg];
                ah[mt][1] = A_h[(mr + g + 8) * 20 + k2o + tg];
                ah[mt][2] = A_h[(mr + g) * 20 + k2o + tg + 4];
                ah[mt][3] = A_h[(mr + g + 8) * 20 + k2o + tg + 4];
                al[mt][0] = A_l[(mr + g) * 20 + k2o + tg];
                al[mt][1] = A_l[(mr + g + 8) * 20 + k2o + tg];
                al[mt][2] = A_l[(mr + g) * 20 + k2o + tg + 4];
                al[mt][3] = A_l[(mr + g + 8) * 20 + k2o + tg + 4];
            }
            #pragma unroll
            for (int nt = 0; nt < 4; nt++) {
                const int nc2 = wn * 32 + nt * 8 + g;
                bh[nt][0] = Bh_[nc2 * 20 + k2o + tg];
                bh[nt][1] = Bh_[nc2 * 20 + k2o + tg + 4];
            }
            #pragma unroll
            for (int mt = 0; mt < 2; mt++)
                #pragma unroll
                for (int nt = 0; nt < 4; nt++) {
                    mma16h(acc[mt][nt], ah[mt], bh[nt]);
                    mma16h(acc[mt][nt], al[mt], bh[nt]);
                }
        }
        __syncthreads();
    }

    if (omode == 3) {
        // V: stage [dim][token] half tile in smem, write coalesced 64B chunks
        __half* sm_h = (__half*)smem;                      // [64 dims][136]
        #pragma unroll
        for (int mt = 0; mt < 2; mt++)
            #pragma unroll
            for (int j2 = 0; j2 < 2; j2++) {
                const int ml = wm * 32 + mt * 16 + g + j2 * 8;
                #pragma unroll
                for (int nt = 0; nt < 4; nt++) {
                    const int nl = wn * 32 + nt * 8 + 2 * tg;
                    const float c0 = acc[mt][nt][j2 * 2 + 0] + bias[n0 + nl];
                    const float c1 = acc[mt][nt][j2 * 2 + 1] + bias[n0 + nl + 1];
                    sm_h[nl * 136 + ml]       = __float2half(c0);
                    sm_h[(nl + 1) * 136 + ml] = __float2half(c1);
                }
            }
        __syncthreads();
        const int b = m0 / LS, t0 = m0 % LS, h = n0 >> 6;
        const int dd = tid >> 2, ch = tid & 3;
        char* dst = (char*)g_Vt + ((((size_t)b * Hh + h) * HD + dd) * LK + t0) * 2 + ch * 64;
        const char* src = (const char*)sm_h + dd * 272 + ch * 64;
        #pragma unroll
        for (int j = 0; j < 4; j++)
            *(uint4*)(dst + j * 16) = *(const uint4*)(src + j * 16);
        return;
    }

    #pragma unroll
    for (int mt = 0; mt < 2; mt++)
        #pragma unroll
        for (int j2 = 0; j2 < 2; j2++) {
            const int m = m0 + wm * 32 + mt * 16 + g + j2 * 8;
            const int b = m / bt, t = m % bt;
            #pragma unroll
            for (int nt = 0; nt < 4; nt++) {
                const int n = n0 + wn * 32 + nt * 8 + 2 * tg;
                const float c0 = acc[mt][nt][j2 * 2 + 0] + bias[n];
                const float c1 = acc[mt][nt][j2 * 2 + 1] + bias[n + 1];
                const int h = n >> 6, dd = n & 63;
                if (omode == 0) {
                    *(float2*)&OutP[(size_t)m * Dd + n] = make_float2(c0, c1);
                } else if (omode == 1) {
                    *(float2*)&g_Q[(((size_t)b * Hh + h) * LQ + t) * HD + dd] = make_float2(c0, c1);
                } else {
                    g_Kh[(((size_t)b * Hh + h) * LK + t) * 32 + (dd >> 1)] = packh(c0, c1);
                }
            }
        }
}

// ---------------- per-token projections (fused 3-in-1) ----------------
__global__ __launch_bounds__(256) void ns_proj(
    const float* __restrict__ x,
    const float* __restrict__ nw0, const float* __restrict__ nb0, float* __restrict__ o0,
    const float* __restrict__ nw1, const float* __restrict__ nb1,
    const float* __restrict__ nw2, const float* __restrict__ nb2)
{
    const int z = blockIdx.z;
    const float* nw = (z == 0) ? nw0 : (z == 1) ? nw1 : nw2;
    const float* nb = (z == 0) ? nb0 : (z == 1) ? nb1 : nb2;

    const int n = blockIdx.x, tid = threadIdx.x;
    const int cgrp = tid & 31, kh = tid >> 5, kbeg = kh * 64;
    const int colb = blockIdx.y * 128;

    __shared__ float xs[8][512];
    __shared__ float red[8][8][128];

    for (int i = tid; i < 8 * 512; i += 256) {
        const int b = i >> 9, k = i & 511;
        xs[b][k] = x[((size_t)b * LL + LS + n) * Dd + k];
    }
    __syncthreads();

    const float4* wp4 = (const float4*)(nw + (size_t)n * Dd * Dd) + (colb >> 2) + cgrp;
    float acc[8][4];
    #pragma unroll
    for (int b = 0; b < 8; b++)
        #pragma unroll
        for (int j = 0; j < 4; j++) acc[b][j] = 0.f;

    for (int k = 0; k < 64; k += 4) {
        float4 w[4];
        #pragma unroll
        for (int u = 0; u < 4; u++) w[u] = wp4[(size_t)(kbeg + k + u) * 128];
        #pragma unroll
        for (int u = 0; u < 4; u++)
            #pragma unroll
            for (int b = 0; b < 8; b++) {
                const float s = xs[b][kbeg + k + u];
                acc[b][0] += s * w[u].x; acc[b][1] += s * w[u].y;
                acc[b][2] += s * w[u].z; acc[b][3] += s * w[u].w;
            }
    }
    #pragma unroll
    for (int b = 0; b < 8; b++)
        *(float4*)&red[kh][b][cgrp * 4] = make_float4(acc[b][0], acc[b][1], acc[b][2], acc[b][3]);
    __syncthreads();

    if (z == 1) {   // K: packed dim pairs
        for (int i = tid; i < 8 * 64; i += 256) {
            const int b = i >> 6, cp = (i & 63) * 2;
            float s0 = 0.f, s1 = 0.f;
            #pragma unroll
            for (int k8 = 0; k8 < 8; k8++) { s0 += red[k8][b][cp]; s1 += red[k8][b][cp + 1]; }
            const int col = colb + cp, h = col >> 6, dd = col & 63;
            s0 += nb[(size_t)n * Dd + col];
            s1 += nb[(size_t)n * Dd + col + 1];
            g_Kh[(((size_t)b * Hh + h) * LK + (LS + n)) * 32 + (dd >> 1)] = packh(s0, s1);
        }
    } else {
        for (int i = tid; i < 8 * 128; i += 256) {
            const int b = i >> 7, c = i & 127;
            float s = 0.f;
            #pragma unroll
            for (int k8 = 0; k8 < 8; k8++) s += red[k8][b][c];
            const int col = colb + c, h = col >> 6, dd = col & 63;
            const float v = s + nb[(size_t)n * Dd + col];
            if (z == 0)
                o0[(((size_t)b * Hh + h) * LQ + LSO + n) * HD + dd] = v;
            else
                g_Vt[(((size_t)b * Hh + h) * HD + dd) * LK + (LS + n)] = __float2half(v);
        }
    }
}

// ---------------- flash attention, full fp16 MMA ----------------
#define AS_V 18432u
#define AS_P 36864u
#define ATTN_SMEM 37376

__global__ __launch_bounds__(128) void attn_tc(
    const float* __restrict__ Q, const int* __restrict__ pad_mask)
{
    extern __shared__ __align__(16) char smc[];
    const uint32_t sb = smem_u32(smc);
    int* padi = (int*)(smc + AS_P);

    const int tid = threadIdx.x, lane = tid & 31, warp = tid >> 5;
    const int g = lane >> 2, tg = lane & 3;
    const int bh = blockIdx.y, b = bh >> 3, h = bh & 7;
    const int q0 = blockIdx.x << 6;
    const int mr = warp * 16;

    const float* Qp = Q + ((size_t)bh * LQ + q0) * HD;
    const char* Kbp = (const char*)g_Kh + (size_t)bh * LK * 128;
    const char* Vbp = (const char*)g_Vt + (size_t)bh * HD * LK * 2;

    unsigned aq[4][4];
    {
        const float* q0p = Qp + (size_t)(mr + g) * HD;
        const float* q1p = Qp + (size_t)(mr + g + 8) * HD;
        #pragma unroll
        for (int kc = 0; kc < 4; kc++) {
            aq[kc][0] = packh(q0p[kc * 16 + 2 * tg] * 0.125f, q0p[kc * 16 + 2 * tg + 1] * 0.125f);
            aq[kc][1] = packh(q1p[kc * 16 + 2 * tg] * 0.125f, q1p[kc * 16 + 2 * tg + 1] * 0.125f);
            aq[kc][2] = packh(q0p[kc * 16 + 8 + 2 * tg] * 0.125f, q0p[kc * 16 + 9 + 2 * tg] * 0.125f);
            aq[kc][3] = packh(q1p[kc * 16 + 8 + 2 * tg] * 0.125f, q1p[kc * 16 + 9 + 2 * tg] * 0.125f);
        }
    }

    float o[8][4];
    #pragma unroll
    for (int nt = 0; nt < 8; nt++)
        #pragma unroll
        for (int j = 0; j < 4; j++) o[nt][j] = 0.f;
    float m_run[2] = {-1e30f, -1e30f};
    float l_run[2] = {0.f, 0.f};

    const int row0 = q0 + mr + g;
    const int ntiles = min(LK >> 6, ((q0 + 63 + DELTA) >> 6) + 1);

#define A_LOAD(t, st) { \
    _Pragma("unroll") \
    for (int i = 0; i < 4; i++) { \
        const int idx = i * 128 + tid; \
        const int r = idx >> 3, ch = idx & 7; \
        cp16(sb + (st) * 9216u + r * 144u + ch * 16u, \
             Kbp + ((size_t)((t) * 64 + r)) * 128 + ch * 16); \
        cp16(sb + AS_V + (st) * 9216u + r * 144u + ch * 16u, \
             Vbp + (size_t)r * (LK * 2) + (t) * 128 + ch * 16); \
    } \
    if ((t) * 64 < LS) { \
        if (tid < 16) \
            cp16(sb + AS_P + (st) * 256u + tid * 16u, \
                 (const char*)(pad_mask + (size_t)b * LS + (t) * 64) + tid * 16); \
    } else { \
        if (tid < 64) padi[(st) * 64 + tid] = 1; \
    } \
    cp_commit(); }

    A_LOAD(0, 0);

    for (int kt = 0; kt < ntiles; kt++) {
        const int nxt = (kt + 1 < ntiles) ? kt + 1 : ntiles - 1;
        A_LOAD(nxt, (kt + 1) & 1);
        cp_wait1();
        __syncthreads();

        const unsigned* Kc = (const unsigned*)(smc + (kt & 1) * 9216u);
        const unsigned* Vc = (const unsigned*)(smc + AS_V + (kt & 1) * 9216u);
        const int*      pc = padi + (kt & 1) * 64;
        const int k0 = kt << 6;

        float sc[8][4];
        #pragma unroll
        for (int nt = 0; nt < 8; nt++)
            #pragma unroll
            for (int j = 0; j < 4; j++) sc[nt][j] = 0.f;

        #pragma unroll
        for (int kc = 0; kc < 4; kc++)
            #pragma unroll
            for (int nt = 0; nt < 8; nt++) {
                unsigned bb[2];
                bb[0] = Kc[(nt * 8 + g) * 36 + kc * 8 + tg];
                bb[1] = Kc[(nt * 8 + g) * 36 + kc * 8 + tg + 4];
                mma16h(sc[nt], aq[kc], bb);
            }

        float mx0 = -1e30f, mx1 = -1e30f;
        #pragma unroll
        for (int nt = 0; nt < 8; nt++) {
            const int cb = k0 + nt * 8 + 2 * tg;
            const int p0 = pc[nt * 8 + 2 * tg];
            const int p1 = pc[nt * 8 + 2 * tg + 1];
            if (cb     > row0 + DELTA     || !p0) sc[nt][0] = -1e9f;
            if (cb + 1 > row0 + DELTA     || !p1) sc[nt][1] = -1e9f;
            if (cb     > row0 + 8 + DELTA || !p0) sc[nt][2] = -1e9f;
            if (cb + 1 > row0 + 8 + DELTA || !p1) sc[nt][3] = -1e9f;
            mx0 = fmaxf(mx0, fmaxf(sc[nt][0], sc[nt][1]));
            mx1 = fmaxf(mx1, fmaxf(sc[nt][2], sc[nt][3]));
        }
        mx0 = fmaxf(mx0, __shfl_xor_sync(0xffffffffu, mx0, 1));
        mx0 = fmaxf(mx0, __shfl_xor_sync(0xffffffffu, mx0, 2));
        mx1 = fmaxf(mx1, __shfl_xor_sync(0xffffffffu, mx1, 1));
        mx1 = fmaxf(mx1, __shfl_xor_sync(0xffffffffu, mx1, 2));

        const float mn0 = fmaxf(m_run[0], mx0), mn1 = fmaxf(m_run[1], mx1);
        const float cr0 = __expf(m_run[0] - mn0), cr1 = __expf(m_run[1] - mn1);

        float ls0 = 0.f, ls1 = 0.f;
        #pragma unroll
        for (int nt = 0; nt < 8; nt++) {
            sc[nt][0] = __expf(sc[nt][0] - mn0); ls0 += sc[nt][0];
            sc[nt][1] = __expf(sc[nt][1] - mn0); ls0 += sc[nt][1];
            sc[nt][2] = __expf(sc[nt][2] - mn1); ls1 += sc[nt][2];
            sc[nt][3] = __expf(sc[nt][3] - mn1); ls1 += sc[nt][3];
        }
        ls0 += __shfl_xor_sync(0xffffffffu, ls0, 1);
        ls0 += __shfl_xor_sync(0xffffffffu, ls0, 2);
        ls1 += __shfl_xor_sync(0xffffffffu, ls1, 1);
        ls1 += __shfl_xor_sync(0xffffffffu, ls1, 2);

        l_run[0] = l_run[0] * cr0 + ls0;
        l_run[1] = l_run[1] * cr1 + ls1;
        m_run[0] = mn0; m_run[1] = mn1;

        #pragma unroll
        for (int nt = 0; nt < 8; nt++) {
            o[nt][0] *= cr0; o[nt][1] *= cr0;
            o[nt][2] *= cr1; o[nt][3] *= cr1;
        }

        #pragma unroll
        for (int kc = 0; kc < 4; kc++) {
            unsigned a[4];
            a[0] = packh(sc[2 * kc][0], sc[2 * kc][1]);
            a[1] = packh(sc[2 * kc][2], sc[2 * kc][3]);
            a[2] = packh(sc[2 * kc + 1][0], sc[2 * kc + 1][1]);
            a[3] = packh(sc[2 * kc + 1][2], sc[2 * kc + 1][3]);
            #pragma unroll
            for (int nt = 0; nt < 8; nt++) {
                unsigned bb[2];
                bb[0] = Vc[(nt * 8 + g) * 36 + kc * 8 + tg];
                bb[1] = Vc[(nt * 8 + g) * 36 + kc * 8 + tg + 4];
                mma16h(o[nt], a, bb);
            }
        }
        __syncthreads();
    }

    // epilogue: write pre-split fp16 hi/lo directly (skips conv_attn)
    const float inv0 = (l_run[0] > 0.f) ? 1.f / l_run[0] : 0.f;
    const float inv1 = (l_run[1] > 0.f) ? 1.f / l_run[1] : 0.f;
    const size_t r0 = (size_t)b * LQ + row0;
    const size_t r1 = r0 + 8;
    #pragma unroll
    for (int nt = 0; nt < 8; nt++) {
        const int k2 = h * 32 + nt * 4 + tg;
        unsigned hh, ll;
        split2h(o[nt][0] * inv0, o[nt][1] * inv0, hh, ll);
        g_a2h[r0 * 256 + k2] = hh;
        g_a2l[r0 * 256 + k2] = ll;
        split2h(o[nt][2] * inv1, o[nt][3] * inv1, hh, ll);
        g_a2h[r1 * 256 + k2] = hh;
        g_a2l[r1 * 256 + k2] = ll;
    }
}

// ---------------------------------------------------------------------------
extern "C" void kernel_launch(void* const* d_in, const int* in_sizes, int n_in,
                              void* d_out, int out_size)
{
    const float* x        = (const float*)d_in[0];
    const int*   pad_mask = (const int*)  d_in[1];
    const float* wq_sw = (const float*)d_in[4];
    const float* wq_sb = (const float*)d_in[5];
    const float* wq_nw = (const float*)d_in[6];
    const float* wq_nb = (const float*)d_in[7];
    const float* wk_sw = (const float*)d_in[8];
    const float* wk_sb = (const float*)d_in[9];
    const float* wk_nw = (const float*)d_in[10];
    const float* wk_nb = (const float*)d_in[11];
    const float* wv_sw = (const float*)d_in[12];
    const float* wv_sb = (const float*)d_in[13];
    const float* wv_nw = (const float*)d_in[14];
    const float* wv_nb = (const float*)d_in[15];
    const float* out_w = (const float*)d_in[16];
    const float* out_b = (const float*)d_in[17];
    float* out = (float*)d_out;

    float* pQ;
    cudaGetSymbolAddress((void**)&pQ, g_Q);

    cudaFuncSetAttribute(gemm5, cudaFuncAttributeMaxDynamicSharedMemorySize, GS_TOT);
    cudaFuncSetAttribute(attn_tc, cudaFuncAttributeMaxDynamicSharedMemorySize, ATTN_SMEM);

    // 1: pre-split x (fp16 hi/lo) + 4 weight matrices (fp16 hi)
    conv_in<<<8704, 256>>>(x, wq_sw, wk_sw, wv_sw, out_w);
    // 2: fused Q+K+V projections; V via smem-transpose, coalesced stores
    gemm5<<<dim3(8, 128, 3), 256, GS_TOT>>>(wk_sb, wv_sb, wq_sb, 0, 1);
    // 3: per-token projections (fused)
    ns_proj<<<dim3(64, 4, 3), 256>>>(x, wq_nw, wq_nb, pQ, wk_nw, wk_nb, wv_nw, wv_nb);
    // 4: attention (fp16 MMA, writes pre-split output)  <-- profiled slot
    attn_tc<<<dim3(LQ / 64, Bc * Hh), 128, ATTN_SMEM>>>(pQ, pad_mask);
    // 5: output projection
    gemm5<<<dim3(8, 36, 1), 256, GS_TOT>>>(out_b, 0, 0, out, 0);
}